// round 14
// baseline (speedup 1.0000x reference)
#include <cuda_runtime.h>
#include <cuda_fp16.h>
#include <cstdint>

#define S_LEN  2048
#define DMODEL 1024
#define NHEAD  16
#define DK     64
#define BATCH  4
#define MTOT   (BATCH * S_LEN)     // 8192

// ---------------- scratch (module-scope device memory) ----------------
__device__ __half g_Aq[MTOT * DMODEL];   // query f16 (later: ctx f16)
__device__ __half g_Ak[MTOT * DMODEL];   // key f16
__device__ __half g_Av[MTOT * DMODEL];   // value f16
__device__ __half g_Qh[BATCH * NHEAD * S_LEN * DK];
__device__ __half g_Kh[BATCH * NHEAD * S_LEN * DK];
__device__ __half g_Vh[BATCH * NHEAD * S_LEN * DK];
__device__ __half g_Wqh[DMODEL * DMODEL];
__device__ __half g_Wkh[DMODEL * DMODEL];
__device__ __half g_Wvh[DMODEL * DMODEL];
__device__ __half g_Woh[DMODEL * DMODEL];

// ---------------- PTX helpers (baseline PTX only) ----------------------
__device__ __forceinline__ uint32_t cvta_smem(const void* p) {
    uint32_t a;
    asm("{ .reg .u64 t; cvta.to.shared.u64 t, %1; cvt.u32.u64 %0, t; }"
        : "=r"(a) : "l"(p));
    return a;
}
__device__ __forceinline__ void cp16(uint32_t dst, const void* src) {
    asm volatile("cp.async.cg.shared.global [%0], [%1], 16;"
                 :: "r"(dst), "l"(src));
}
#define CP_COMMIT() asm volatile("cp.async.commit_group;" ::: "memory")
#define CP_WAIT(n)  asm volatile("cp.async.wait_group %0;" :: "n"(n) : "memory")

__device__ __forceinline__ void ldsm4(uint32_t* r, uint32_t addr) {
    asm volatile("ldmatrix.sync.aligned.m8n8.x4.shared.b16 {%0,%1,%2,%3}, [%4];"
                 : "=r"(r[0]), "=r"(r[1]), "=r"(r[2]), "=r"(r[3]) : "r"(addr));
}
__device__ __forceinline__ void ldsm4t(uint32_t* r, uint32_t addr) {
    asm volatile("ldmatrix.sync.aligned.m8n8.x4.trans.shared.b16 {%0,%1,%2,%3}, [%4];"
                 : "=r"(r[0]), "=r"(r[1]), "=r"(r[2]), "=r"(r[3]) : "r"(addr));
}
__device__ __forceinline__ void mma16816(float* d, const uint32_t* a,
                                         uint32_t b0, uint32_t b1) {
    asm volatile(
        "mma.sync.aligned.m16n8k16.row.col.f32.f16.f16.f32 "
        "{%0,%1,%2,%3}, {%4,%5,%6,%7}, {%8,%9}, {%0,%1,%2,%3};"
        : "+f"(d[0]), "+f"(d[1]), "+f"(d[2]), "+f"(d[3])
        : "r"(a[0]), "r"(a[1]), "r"(a[2]), "r"(a[3]), "r"(b0), "r"(b1));
}
__device__ __forceinline__ float ex2(float x) {
    float y;
    asm("ex2.approx.f32 %0, %1;" : "=f"(y) : "f"(x));
    return y;
}

__device__ __forceinline__ uint2 pack_hi(float4 v) {
    __half h0 = __float2half_rn(v.x), h1 = __float2half_rn(v.y);
    __half h2 = __float2half_rn(v.z), h3 = __float2half_rn(v.w);
    uint2 H;
    H.x = (uint32_t)__half_as_ushort(h0) | ((uint32_t)__half_as_ushort(h1) << 16);
    H.y = (uint32_t)__half_as_ushort(h2) | ((uint32_t)__half_as_ushort(h3) << 16);
    return H;
}

// ---------------- single consolidated split kernel (MLP=4) --------------
#define ACT_BLKS  2048        // (MTOT*DMODEL/4)/256/4
#define W_BLKS    256         // (DMODEL*DMODEL/4)/256/4
#define SPLIT_GRID (3 * ACT_BLKS + 4 * W_BLKS)

__global__ __launch_bounds__(256) void split_all(
    const float4* __restrict__ q, const float4* __restrict__ k,
    const float4* __restrict__ v,
    const float4* __restrict__ wq, const float4* __restrict__ wk,
    const float4* __restrict__ wv, const float4* __restrict__ wo,
    uint2* __restrict__ aq, uint2* __restrict__ ak, uint2* __restrict__ av,
    uint2* __restrict__ wqh, uint2* __restrict__ wkh,
    uint2* __restrict__ wvh, uint2* __restrict__ woh)
{
    const int b = blockIdx.x, t = threadIdx.x;
    const float4* src;
    uint2* dst;
    int base;
    if (b < 3 * ACT_BLKS) {
        const int which = b / ACT_BLKS;
        base = (b % ACT_BLKS) * 1024 + t;
        src = which == 0 ? q : (which == 1 ? k : v);
        dst = which == 0 ? aq : (which == 1 ? ak : av);
    } else {
        const int wb = b - 3 * ACT_BLKS;
        const int which = wb / W_BLKS;
        base = (wb % W_BLKS) * 1024 + t;
        src = which == 0 ? wq : (which == 1 ? wk : (which == 2 ? wv : wo));
        dst = which == 0 ? wqh : (which == 1 ? wkh : (which == 2 ? wvh : woh));
    }
    float4 v0 = src[base];
    float4 v1 = src[base + 256];
    float4 v2 = src[base + 512];
    float4 v3 = src[base + 768];
    dst[base]       = pack_hi(v0);
    dst[base + 256] = pack_hi(v1);
    dst[base + 512] = pack_hi(v2);
    dst[base + 768] = pack_hi(v3);
}

// ---------------- HMMA projection GEMM (128x64 tile, 3 CTAs/SM) ---------
// Single __syncthreads per K-chunk (trailing barrier removed: the top
// barrier of the next chunk already orders compute(c) before the load
// that overwrites buffer c&1).
#define TILE_M 128
#define TILE_N 64
#define KCH    64
#define NC     (DMODEL / KCH)  // 16
#define PITCH  72              // halves per smem row (144B)
#define ROWB   144
#define A_OFF  0
#define B_OFF  (128 * ROWB)              // 18432
#define STG_B  (B_OFF + 64 * ROWB)       // 27648
#define SMEM_GEMM (2 * STG_B)            // 55296

template <int QKV>
__global__ __launch_bounds__(128, 3) void proj_gemm_mma(
    const __half* __restrict__ A0, const __half* __restrict__ A1,
    const __half* __restrict__ A2,
    const __half* __restrict__ W0, const __half* __restrict__ W1,
    const __half* __restrict__ W2,
    const float* __restrict__ b0, const float* __restrict__ b1,
    const float* __restrict__ b2,
    __half* __restrict__ C0, __half* __restrict__ C1,
    __half* __restrict__ C2, float* __restrict__ Cf)
{
    extern __shared__ char sm[];
    const uint32_t smb = cvta_smem(sm);
    const int tid = threadIdx.x;
    const int wid = tid >> 5, lane = tid & 31;
    const int wm = wid & 1;
    const int wn = wid >> 1;
    const int m0 = blockIdx.y * TILE_M;
    const int n0 = blockIdx.x * TILE_N;

    const __half* Ahg; const __half* Whg; const float* bias; __half* Ch;
    if (QKV) {
        const int z = blockIdx.z;
        Ahg  = z == 0 ? A0 : (z == 1 ? A1 : A2);
        Whg  = z == 0 ? W0 : (z == 1 ? W1 : W2);
        bias = z == 0 ? b0 : (z == 1 ? b1 : b2);
        Ch   = z == 0 ? C0 : (z == 1 ? C1 : C2);
    } else {
        Ahg = A0; Whg = W0; bias = b0; Ch = nullptr;
    }

    const int laneA = (lane & 15) * PITCH + ((lane >> 4) & 1) * 8;
    const int laneB = ((lane & 7) + ((lane >> 4) & 1) * 8) * PITCH + ((lane >> 3) & 1) * 8;

    auto load_chunk = [&](int c, int stage) {
        const uint32_t sbase = smb + (uint32_t)stage * STG_B;
#pragma unroll
        for (int i = 0; i < 8; i++) {
            int slot = tid + i * 128;
            int row = slot >> 3, quad = slot & 7;
            uint32_t soff = (uint32_t)row * ROWB + (uint32_t)quad * 16u;
            size_t goff = (size_t)(m0 + row) * DMODEL + c * KCH + quad * 8;
            cp16(sbase + A_OFF + soff, Ahg + goff);
        }
#pragma unroll
        for (int i = 0; i < 4; i++) {
            int slot = tid + i * 128;
            int row = slot >> 3, quad = slot & 7;
            uint32_t soff = (uint32_t)row * ROWB + (uint32_t)quad * 16u;
            size_t goff = (size_t)(n0 + row) * DMODEL + c * KCH + quad * 8;
            cp16(sbase + B_OFF + soff, Whg + goff);
        }
    };

    float acc[4][4][4];
#pragma unroll
    for (int mf = 0; mf < 4; mf++)
#pragma unroll
        for (int nf = 0; nf < 4; nf++)
#pragma unroll
            for (int j = 0; j < 4; j++) acc[mf][nf][j] = 0.0f;

    load_chunk(0, 0); CP_COMMIT();

    for (int c = 0; c < NC; c++) {
        CP_WAIT(0);
        __syncthreads();          // orders compute(c-1) before load(c+1) too
        if (c + 1 < NC) {
            load_chunk(c + 1, (c + 1) & 1);
            CP_COMMIT();
        }

        const uint32_t sbase = smb + (uint32_t)(c & 1) * STG_B;

#pragma unroll
        for (int ks = 0; ks < 4; ks++) {
            const int kk = ks * 16;
            uint32_t ah[4][4], bh[8];
#pragma unroll
            for (int mf = 0; mf < 4; mf++) {
                uint32_t idx = (uint32_t)((wm * 64 + mf * 16) * PITCH + kk + laneA) * 2;
                ldsm4(ah[mf], sbase + A_OFF + idx);
            }
#pragma unroll
            for (int nf2 = 0; nf2 < 2; nf2++) {
                uint32_t idx = (uint32_t)((wn * 32 + nf2 * 16) * PITCH + kk + laneB) * 2;
                ldsm4(bh + nf2 * 4, sbase + B_OFF + idx);
            }
#pragma unroll
            for (int mf = 0; mf < 4; mf++)
#pragma unroll
                for (int nf = 0; nf < 4; nf++) {
                    int bi = (nf >> 1) * 4 + (nf & 1) * 2;
                    mma16816(acc[mf][nf], ah[mf], bh[bi], bh[bi + 1]);
                }
        }
        // trailing __syncthreads removed (redundant with next top barrier)
    }

    // epilogue
#pragma unroll
    for (int mf = 0; mf < 4; mf++) {
#pragma unroll
        for (int nf = 0; nf < 4; nf++) {
            int m = m0 + wm * 64 + mf * 16 + (lane >> 2);
            int n = n0 + wn * 32 + nf * 8 + (lane & 3) * 2;
            float bx = bias[n], by = bias[n + 1];
#pragma unroll
            for (int hh = 0; hh < 2; hh++) {
                int mm = m + hh * 8;
                float vx = acc[mf][nf][hh * 2 + 0] + bx;
                float vy = acc[mf][nf][hh * 2 + 1] + by;
                if (QKV) {
                    int b = mm >> 11, s = mm & (S_LEN - 1);
                    int h = n >> 6, d = n & (DK - 1);
                    size_t idx = ((size_t)((b << 4) + h) * S_LEN + s) * DK + d;
                    *(__half2*)(Ch + idx) = __floats2half2_rn(vx, vy);
                } else {
                    float2 v; v.x = vx; v.y = vy;
                    *(float2*)(Cf + (size_t)mm * DMODEL + n) = v;
                }
            }
        }
    }
}

// ---------------- HMMA causal flash attention (paired-q KV sharing) -----
#define FPITCH 72                          // halves
#define FROWB  144
#define QBUF   (64 * FROWB)                // 9216 B
#define KVBUF  (128 * FROWB)               // 18432 B
#define OFF_QA 0
#define OFF_QB QBUF
#define OFF_KV (2 * QBUF)                  // 18432
#define KVSTG  (2 * KVBUF)                 // 36864 (K + V)
#define SMEM_FLASH (OFF_KV + 2 * KVSTG)    // 92160

__global__ __launch_bounds__(128, 2) void flash_mma(
    const __half* __restrict__ Qh,
    const __half* __restrict__ Kh, const __half* __restrict__ Vh,
    __half* __restrict__ Oh)
{
    extern __shared__ char sm[];
    const uint32_t smb = cvta_smem(sm);
    const int tid = threadIdx.x;
    const int w = tid >> 5, lane = tid & 31;
    const int pair = blockIdx.x;          // 0..15
    const int bh = blockIdx.y;            // 0..63

    const size_t seqbase = (size_t)bh * S_LEN * DK;

    const int qa = pair, qb = 31 - pair;  // qa < qb always
    const int q0a = qa * 64, q0b = qb * 64;
    const int Ta = (qa + 2) >> 1, Tb = (qb + 2) >> 1;

    const int laneA = (lane & 15) * FPITCH + ((lane >> 4) & 1) * 8;
    const int laneB = ((lane & 7) + ((lane >> 4) & 1) * 8) * FPITCH + ((lane >> 3) & 1) * 8;
    const int laneV = ((lane & 7) + ((lane >> 3) & 1) * 8) * FPITCH + ((lane >> 4) & 1) * 8;

    const float cs = 0.18033688f;         // (1/8) * log2(e)
    const int b = bh >> 4, h = bh & 15;
    const int cbase = (lane & 3) * 2;

    // load both Q tiles (64 rows each)
#pragma unroll
    for (int i = 0; i < 4; i++) {
        int slot = tid + i * 128;
        int r = slot >> 3, quad = slot & 7;
        uint32_t so = (uint32_t)r * FROWB + (uint32_t)quad * 16u;
        cp16(smb + OFF_QA + so, Qh + seqbase + (size_t)(q0a + r) * DK + quad * 8);
        cp16(smb + OFF_QB + so, Qh + seqbase + (size_t)(q0b + r) * DK + quad * 8);
    }
    auto load_tile = [&](int kt, int stage) {
        const uint32_t sb = smb + OFF_KV + (uint32_t)stage * KVSTG;
#pragma unroll
        for (int i = 0; i < 8; i++) {
            int slot = tid + i * 128;
            int r = slot >> 3, quad = slot & 7;   // r: 0..127
            uint32_t so = (uint32_t)r * FROWB + (uint32_t)quad * 16u;
            size_t g = seqbase + (size_t)(kt * 128 + r) * DK + quad * 8;
            cp16(sb + 0 * KVBUF + so, Kh + g);
            cp16(sb + 1 * KVBUF + so, Vh + g);
        }
    };
    load_tile(0, 0); CP_COMMIT();

    uint32_t qhfA[4][4], qhfB[4][4];
    float oaccA[8][4], oaccB[8][4];
#pragma unroll
    for (int nf = 0; nf < 8; nf++)
#pragma unroll
        for (int j = 0; j < 4; j++) { oaccA[nf][j] = 0.0f; oaccB[nf][j] = 0.0f; }
    float mA0 = -1e30f, mA1 = -1e30f, lA0 = 0.0f, lA1 = 0.0f;
    float mB0 = -1e30f, mB1 = -1e30f, lB0 = 0.0f, lB1 = 0.0f;

    auto process = [&](const uint32_t (&qhf)[4][4], float (&oacc)[8][4],
                       float& m0r, float& m1r, float& l0r, float& l1r,
                       int q0, bool lastTile, uint32_t kvb, int kt) {
        const int rbase = q0 + w * 16 + (lane >> 2);

        // ---- S = Q K^T ----
        float sacc[16][4];
#pragma unroll
        for (int nf = 0; nf < 16; nf++)
#pragma unroll
            for (int j = 0; j < 4; j++) sacc[nf][j] = 0.0f;

#pragma unroll
        for (int ks = 0; ks < 4; ks++) {
            uint32_t kb[32];
#pragma unroll
            for (int nb = 0; nb < 8; nb++) {
                uint32_t a = kvb + (uint32_t)((nb * 16) * FPITCH + ks * 16 + laneB) * 2;
                ldsm4(kb + nb * 4, a);
            }
#pragma unroll
            for (int nf = 0; nf < 16; nf++) {
                int bi = (nf >> 1) * 4 + (nf & 1) * 2;
                mma16816(sacc[nf], qhf[ks], kb[bi], kb[bi + 1]);
            }
        }

        // ---- scale (+ causal mask on the last tile) ----
        if (lastTile) {
#pragma unroll
            for (int nf = 0; nf < 16; nf++) {
#pragma unroll
                for (int j = 0; j < 4; j++) {
                    int col = kt * 128 + nf * 8 + cbase + (j & 1);
                    int row = rbase + ((j >> 1) << 3);
                    sacc[nf][j] = (col <= row) ? sacc[nf][j] * cs : -1e30f;
                }
            }
        } else {
#pragma unroll
            for (int nf = 0; nf < 16; nf++)
#pragma unroll
                for (int j = 0; j < 4; j++) sacc[nf][j] *= cs;
        }

        // ---- online softmax (base-2) ----
        float mx0 = -1e30f, mx1 = -1e30f;
#pragma unroll
        for (int nf = 0; nf < 16; nf++) {
            mx0 = fmaxf(mx0, fmaxf(sacc[nf][0], sacc[nf][1]));
            mx1 = fmaxf(mx1, fmaxf(sacc[nf][2], sacc[nf][3]));
        }
        mx0 = fmaxf(mx0, __shfl_xor_sync(0xffffffffu, mx0, 1));
        mx0 = fmaxf(mx0, __shfl_xor_sync(0xffffffffu, mx0, 2));
        mx1 = fmaxf(mx1, __shfl_xor_sync(0xffffffffu, mx1, 1));
        mx1 = fmaxf(mx1, __shfl_xor_sync(0xffffffffu, mx1, 2));

        float mn0 = fmaxf(m0r, mx0), mn1 = fmaxf(m1r, mx1);
        float c0 = ex2(m0r - mn0), c1 = ex2(m1r - mn1);
        m0r = mn0; m1r = mn1;

        uint32_t pHa[16], pHb[16];
        float ls0 = 0.0f, ls1 = 0.0f;
#pragma unroll
        for (int nf = 0; nf < 16; nf++) {
            float p0 = ex2(sacc[nf][0] - mn0);
            float p1 = ex2(sacc[nf][1] - mn0);
            float p2 = ex2(sacc[nf][2] - mn1);
            float p3 = ex2(sacc[nf][3] - mn1);
            ls0 += p0 + p1;
            ls1 += p2 + p3;
            __half2 h01 = __floats2half2_rn(p0, p1);
            __half2 h23 = __floats2half2_rn(p2, p3);
            pHa[nf] = *(uint32_t*)&h01;
            pHb[nf] = *(uint32_t*)&h23;
        }
        ls0 += __shfl_xor_sync(0xffffffffu, ls0, 1);
        ls0 += __shfl_xor_sync(0xffffffffu, ls0, 2);
        ls1 += __shfl_xor_sync(0xffffffffu, ls1, 1);
        ls1 += __shfl_xor_sync(0xffffffffu, ls1, 2);
        l0r = l0r * c0 + ls0;
        l1r = l1r * c1 + ls1;
#pragma unroll
        for (int nf = 0; nf < 8; nf++) {
            oacc[nf][0] *= c0; oacc[nf][1] *= c0;
            oacc[nf][2] *= c1; oacc[nf][3] *= c1;
        }

        // ---- O += P V ----
        const uint32_t vbb = kvb + KVBUF;
#pragma unroll
        for (int ks = 0; ks < 8; ks++) {
            uint32_t vb[16];
#pragma unroll
            for (int nb = 0; nb < 4; nb++) {
                uint32_t a = vbb + (uint32_t)((ks * 16) * FPITCH + nb * 16 + laneV) * 2;
                ldsm4t(vb + nb * 4, a);
            }
            uint32_t pa[4] = { pHa[2 * ks], pHb[2 * ks],
                               pHa[2 * ks + 1], pHb[2 * ks + 1] };
#pragma unroll
            for (int nf = 0; nf < 8; nf++) {
                int bi = (nf >> 1) * 4 + (nf & 1) * 2;
                mma16816(oacc[nf], pa, vb[bi], vb[bi + 1]);
            }
        }
    };

    for (int kt = 0; kt < Tb; kt++) {
        CP_WAIT(0);
        __syncthreads();

        // issue the next-tile prefetch FIRST so it shadows all compute
        if (kt + 1 < Tb) {
            load_tile(kt + 1, (kt + 1) & 1);
            CP_COMMIT();
        }
        if (kt == 0) {
#pragma unroll
            for (int ks = 0; ks < 4; ks++) {
                uint32_t off = (uint32_t)((w * 16) * FPITCH + ks * 16 + laneA) * 2;
                ldsm4(qhfA[ks], smb + OFF_QA + off);
                ldsm4(qhfB[ks], smb + OFF_QB + off);
            }
        }

        const uint32_t kvb = smb + OFF_KV + (uint32_t)(kt & 1) * KVSTG;

        process(qhfB, oaccB, mB0, mB1, lB0, lB1, q0b, kt == Tb - 1, kvb, kt);
        if (kt < Ta)
            process(qhfA, oaccA, mA0, mA1, lA0, lA1, q0a, kt == Ta - 1, kvb, kt);
    }

    // ---- epilogue: write fp16 context [B,S,1024] for both q-tiles ----
#pragma unroll
    for (int which = 0; which < 2; which++) {
        float (*oacc)[4] = which ? oaccB : oaccA;
        const float inv0 = 1.0f / (which ? lB0 : lA0);
        const float inv1 = 1.0f / (which ? lB1 : lA1);
        const int q0 = which ? q0b : q0a;
        const int s0 = q0 + w * 16 + (lane >> 2);
#pragma unroll
        for (int nf = 0; nf < 8; nf++) {
            int col = h * DK + nf * 8 + cbase;
#pragma unroll
            for (int hh = 0; hh < 2; hh++) {
                int s = s0 + hh * 8;
                float vx = oacc[nf][hh * 2 + 0] * (hh ? inv1 : inv0);
                float vy = oacc[nf][hh * 2 + 1] * (hh ? inv1 : inv0);
                size_t idx = ((size_t)(b * S_LEN + s)) * DMODEL + col;
                *(__half2*)(Oh + idx) = __floats2half2_rn(vx, vy);
            }
        }
    }
}

// ===========================================================================
extern "C" void kernel_launch(void* const* d_in, const int* in_sizes, int n_in,
                              void* d_out, int out_size)
{
    const float* query = (const float*)d_in[0];
    const float* key   = (const float*)d_in[1];
    const float* value = (const float*)d_in[2];
    // d_in[3] = causal mask — handled analytically.
    const float* Wq = (const float*)d_in[4];
    const float* bq = (const float*)d_in[5];
    const float* Wk = (const float*)d_in[6];
    const float* bk = (const float*)d_in[7];
    const float* Wv = (const float*)d_in[8];
    const float* bv = (const float*)d_in[9];
    const float* Wo = (const float*)d_in[10];
    const float* bo = (const float*)d_in[11];
    float* out = (float*)d_out;

    __half *Aq, *Ak, *Av, *Qh, *Kh, *Vh, *Wqh, *Wkh, *Wvh, *Woh;
    cudaGetSymbolAddress((void**)&Aq, g_Aq);
    cudaGetSymbolAddress((void**)&Ak, g_Ak);
    cudaGetSymbolAddress((void**)&Av, g_Av);
    cudaGetSymbolAddress((void**)&Qh, g_Qh);
    cudaGetSymbolAddress((void**)&Kh, g_Kh);
    cudaGetSymbolAddress((void**)&Vh, g_Vh);
    cudaGetSymbolAddress((void**)&Wqh, g_Wqh);
    cudaGetSymbolAddress((void**)&Wkh, g_Wkh);
    cudaGetSymbolAddress((void**)&Wvh, g_Wvh);
    cudaGetSymbolAddress((void**)&Woh, g_Woh);

    cudaFuncSetAttribute(proj_gemm_mma<1>,
                         cudaFuncAttributeMaxDynamicSharedMemorySize, SMEM_GEMM);
    cudaFuncSetAttribute(proj_gemm_mma<0>,
                         cudaFuncAttributeMaxDynamicSharedMemorySize, SMEM_GEMM);
    cudaFuncSetAttribute(flash_mma,
                         cudaFuncAttributeMaxDynamicSharedMemorySize, SMEM_FLASH);

    // one consolidated conversion pass
    split_all<<<SPLIT_GRID, 256>>>(
        (const float4*)query, (const float4*)key, (const float4*)value,
        (const float4*)Wq, (const float4*)Wk, (const float4*)Wv, (const float4*)Wo,
        (uint2*)Aq, (uint2*)Ak, (uint2*)Av,
        (uint2*)Wqh, (uint2*)Wkh, (uint2*)Wvh, (uint2*)Woh);

    // Q, K, V projections batched in one launch
    dim3 gq(DMODEL / TILE_N, MTOT / TILE_M, 3);   // (16, 64, 3)
    proj_gemm_mma<1><<<gq, 128, SMEM_GEMM>>>(
        Aq, Ak, Av, Wqh, Wkh, Wvh, bq, bk, bv, Qh, Kh, Vh, nullptr);

    // attention: paired q-tiles, writes fp16 context into Aq
    flash_mma<<<dim3(16, BATCH * NHEAD), 128, SMEM_FLASH>>>(Qh, Kh, Vh, Aq);

    // out = Ctx @ Wo^T + bo (fp32 out)
    dim3 go(DMODEL / TILE_N, MTOT / TILE_M, 1);   // (16, 64)
    proj_gemm_mma<0><<<go, 128, SMEM_GEMM>>>(
        Aq, nullptr, nullptr, Woh, nullptr, nullptr,
        bo, nullptr, nullptr, nullptr, nullptr, nullptr, out);
}

// round 15
// speedup vs baseline: 1.0065x; 1.0065x over previous
#include <cuda_runtime.h>
#include <cuda_fp16.h>
#include <cstdint>

#define S_LEN  2048
#define DMODEL 1024
#define NHEAD  16
#define DK     64
#define BATCH  4
#define MTOT   (BATCH * S_LEN)     // 8192

// ---------------- scratch (module-scope device memory) ----------------
__device__ __half g_Aq[MTOT * DMODEL];   // query f16 (later: ctx f16)
__device__ __half g_Ak[MTOT * DMODEL];   // key f16
__device__ __half g_Av[MTOT * DMODEL];   // value f16
__device__ __half g_Qh[BATCH * NHEAD * S_LEN * DK];
__device__ __half g_Kh[BATCH * NHEAD * S_LEN * DK];
__device__ __half g_Vh[BATCH * NHEAD * S_LEN * DK];
__device__ __half g_Wqh[DMODEL * DMODEL];
__device__ __half g_Wkh[DMODEL * DMODEL];
__device__ __half g_Wvh[DMODEL * DMODEL];
__device__ __half g_Woh[DMODEL * DMODEL];

// ---------------- PTX helpers (baseline PTX only) ----------------------
__device__ __forceinline__ uint32_t cvta_smem(const void* p) {
    uint32_t a;
    asm("{ .reg .u64 t; cvta.to.shared.u64 t, %1; cvt.u32.u64 %0, t; }"
        : "=r"(a) : "l"(p));
    return a;
}
__device__ __forceinline__ void cp16(uint32_t dst, const void* src) {
    asm volatile("cp.async.cg.shared.global [%0], [%1], 16;"
                 :: "r"(dst), "l"(src));
}
#define CP_COMMIT() asm volatile("cp.async.commit_group;" ::: "memory")
#define CP_WAIT(n)  asm volatile("cp.async.wait_group %0;" :: "n"(n) : "memory")

__device__ __forceinline__ void ldsm4(uint32_t* r, uint32_t addr) {
    asm volatile("ldmatrix.sync.aligned.m8n8.x4.shared.b16 {%0,%1,%2,%3}, [%4];"
                 : "=r"(r[0]), "=r"(r[1]), "=r"(r[2]), "=r"(r[3]) : "r"(addr));
}
__device__ __forceinline__ void ldsm4t(uint32_t* r, uint32_t addr) {
    asm volatile("ldmatrix.sync.aligned.m8n8.x4.trans.shared.b16 {%0,%1,%2,%3}, [%4];"
                 : "=r"(r[0]), "=r"(r[1]), "=r"(r[2]), "=r"(r[3]) : "r"(addr));
}
__device__ __forceinline__ void mma16816(float* d, const uint32_t* a,
                                         uint32_t b0, uint32_t b1) {
    asm volatile(
        "mma.sync.aligned.m16n8k16.row.col.f32.f16.f16.f32 "
        "{%0,%1,%2,%3}, {%4,%5,%6,%7}, {%8,%9}, {%0,%1,%2,%3};"
        : "+f"(d[0]), "+f"(d[1]), "+f"(d[2]), "+f"(d[3])
        : "r"(a[0]), "r"(a[1]), "r"(a[2]), "r"(a[3]), "r"(b0), "r"(b1));
}
__device__ __forceinline__ float ex2(float x) {
    float y;
    asm("ex2.approx.f32 %0, %1;" : "=f"(y) : "f"(x));
    return y;
}

__device__ __forceinline__ uint2 pack_hi(float4 v) {
    __half h0 = __float2half_rn(v.x), h1 = __float2half_rn(v.y);
    __half h2 = __float2half_rn(v.z), h3 = __float2half_rn(v.w);
    uint2 H;
    H.x = (uint32_t)__half_as_ushort(h0) | ((uint32_t)__half_as_ushort(h1) << 16);
    H.y = (uint32_t)__half_as_ushort(h2) | ((uint32_t)__half_as_ushort(h3) << 16);
    return H;
}

template <int N> struct IC { static constexpr int value = N; };

// ---------------- single consolidated split kernel (MLP=4) --------------
#define ACT_BLKS  2048        // (MTOT*DMODEL/4)/256/4
#define W_BLKS    256         // (DMODEL*DMODEL/4)/256/4
#define SPLIT_GRID (3 * ACT_BLKS + 4 * W_BLKS)

__global__ __launch_bounds__(256) void split_all(
    const float4* __restrict__ q, const float4* __restrict__ k,
    const float4* __restrict__ v,
    const float4* __restrict__ wq, const float4* __restrict__ wk,
    const float4* __restrict__ wv, const float4* __restrict__ wo,
    uint2* __restrict__ aq, uint2* __restrict__ ak, uint2* __restrict__ av,
    uint2* __restrict__ wqh, uint2* __restrict__ wkh,
    uint2* __restrict__ wvh, uint2* __restrict__ woh)
{
    const int b = blockIdx.x, t = threadIdx.x;
    const float4* src;
    uint2* dst;
    int base;
    if (b < 3 * ACT_BLKS) {
        const int which = b / ACT_BLKS;
        base = (b % ACT_BLKS) * 1024 + t;
        src = which == 0 ? q : (which == 1 ? k : v);
        dst = which == 0 ? aq : (which == 1 ? ak : av);
    } else {
        const int wb = b - 3 * ACT_BLKS;
        const int which = wb / W_BLKS;
        base = (wb % W_BLKS) * 1024 + t;
        src = which == 0 ? wq : (which == 1 ? wk : (which == 2 ? wv : wo));
        dst = which == 0 ? wqh : (which == 1 ? wkh : (which == 2 ? wvh : woh));
    }
    float4 v0 = src[base];
    float4 v1 = src[base + 256];
    float4 v2 = src[base + 512];
    float4 v3 = src[base + 768];
    dst[base]       = pack_hi(v0);
    dst[base + 256] = pack_hi(v1);
    dst[base + 512] = pack_hi(v2);
    dst[base + 768] = pack_hi(v3);
}

// ---------------- HMMA projection GEMM (128x64 tile, 3 CTAs/SM) ---------
#define TILE_M 128
#define TILE_N 64
#define KCH    64
#define NC     (DMODEL / KCH)  // 16
#define PITCH  72              // halves per smem row (144B)
#define ROWB   144
#define A_OFF  0
#define B_OFF  (128 * ROWB)              // 18432
#define STG_B  (B_OFF + 64 * ROWB)       // 27648
#define SMEM_GEMM (2 * STG_B)            // 55296

template <int QKV>
__global__ __launch_bounds__(128, 3) void proj_gemm_mma(
    const __half* __restrict__ A0, const __half* __restrict__ A1,
    const __half* __restrict__ A2,
    const __half* __restrict__ W0, const __half* __restrict__ W1,
    const __half* __restrict__ W2,
    const float* __restrict__ b0, const float* __restrict__ b1,
    const float* __restrict__ b2,
    __half* __restrict__ C0, __half* __restrict__ C1,
    __half* __restrict__ C2, float* __restrict__ Cf)
{
    extern __shared__ char sm[];
    const uint32_t smb = cvta_smem(sm);
    const int tid = threadIdx.x;
    const int wid = tid >> 5, lane = tid & 31;
    const int wm = wid & 1;
    const int wn = wid >> 1;
    const int m0 = blockIdx.y * TILE_M;
    const int n0 = blockIdx.x * TILE_N;

    const __half* Ahg; const __half* Whg; const float* bias; __half* Ch;
    if (QKV) {
        const int z = blockIdx.z;
        Ahg  = z == 0 ? A0 : (z == 1 ? A1 : A2);
        Whg  = z == 0 ? W0 : (z == 1 ? W1 : W2);
        bias = z == 0 ? b0 : (z == 1 ? b1 : b2);
        Ch   = z == 0 ? C0 : (z == 1 ? C1 : C2);
    } else {
        Ahg = A0; Whg = W0; bias = b0; Ch = nullptr;
    }

    const int laneA = (lane & 15) * PITCH + ((lane >> 4) & 1) * 8;
    const int laneB = ((lane & 7) + ((lane >> 4) & 1) * 8) * PITCH + ((lane >> 3) & 1) * 8;

    auto load_chunk = [&](int c, int stage) {
        const uint32_t sbase = smb + (uint32_t)stage * STG_B;
#pragma unroll
        for (int i = 0; i < 8; i++) {
            int slot = tid + i * 128;
            int row = slot >> 3, quad = slot & 7;
            uint32_t soff = (uint32_t)row * ROWB + (uint32_t)quad * 16u;
            size_t goff = (size_t)(m0 + row) * DMODEL + c * KCH + quad * 8;
            cp16(sbase + A_OFF + soff, Ahg + goff);
        }
#pragma unroll
        for (int i = 0; i < 4; i++) {
            int slot = tid + i * 128;
            int row = slot >> 3, quad = slot & 7;
            uint32_t soff = (uint32_t)row * ROWB + (uint32_t)quad * 16u;
            size_t goff = (size_t)(n0 + row) * DMODEL + c * KCH + quad * 8;
            cp16(sbase + B_OFF + soff, Whg + goff);
        }
    };

    float acc[4][4][4];
#pragma unroll
    for (int mf = 0; mf < 4; mf++)
#pragma unroll
        for (int nf = 0; nf < 4; nf++)
#pragma unroll
            for (int j = 0; j < 4; j++) acc[mf][nf][j] = 0.0f;

    load_chunk(0, 0); CP_COMMIT();

    for (int c = 0; c < NC; c++) {
        CP_WAIT(0);
        __syncthreads();          // also orders compute(c-1) before load(c+1)
        if (c + 1 < NC) {
            load_chunk(c + 1, (c + 1) & 1);
            CP_COMMIT();
        }

        const uint32_t sbase = smb + (uint32_t)(c & 1) * STG_B;

#pragma unroll
        for (int ks = 0; ks < 4; ks++) {
            const int kk = ks * 16;
            uint32_t ah[4][4], bh[8];
#pragma unroll
            for (int mf = 0; mf < 4; mf++) {
                uint32_t idx = (uint32_t)((wm * 64 + mf * 16) * PITCH + kk + laneA) * 2;
                ldsm4(ah[mf], sbase + A_OFF + idx);
            }
#pragma unroll
            for (int nf2 = 0; nf2 < 2; nf2++) {
                uint32_t idx = (uint32_t)((wn * 32 + nf2 * 16) * PITCH + kk + laneB) * 2;
                ldsm4(bh + nf2 * 4, sbase + B_OFF + idx);
            }
#pragma unroll
            for (int mf = 0; mf < 4; mf++)
#pragma unroll
                for (int nf = 0; nf < 4; nf++) {
                    int bi = (nf >> 1) * 4 + (nf & 1) * 2;
                    mma16816(acc[mf][nf], ah[mf], bh[bi], bh[bi + 1]);
                }
        }
    }

    // epilogue
#pragma unroll
    for (int mf = 0; mf < 4; mf++) {
#pragma unroll
        for (int nf = 0; nf < 4; nf++) {
            int m = m0 + wm * 64 + mf * 16 + (lane >> 2);
            int n = n0 + wn * 32 + nf * 8 + (lane & 3) * 2;
            float bx = bias[n], by = bias[n + 1];
#pragma unroll
            for (int hh = 0; hh < 2; hh++) {
                int mm = m + hh * 8;
                float vx = acc[mf][nf][hh * 2 + 0] + bx;
                float vy = acc[mf][nf][hh * 2 + 1] + by;
                if (QKV) {
                    int b = mm >> 11, s = mm & (S_LEN - 1);
                    int h = n >> 6, d = n & (DK - 1);
                    size_t idx = ((size_t)((b << 4) + h) * S_LEN + s) * DK + d;
                    *(__half2*)(Ch + idx) = __floats2half2_rn(vx, vy);
                } else {
                    float2 v; v.x = vx; v.y = vy;
                    *(float2*)(Cf + (size_t)mm * DMODEL + n) = v;
                }
            }
        }
    }
}

// ---------------- HMMA causal flash attention (paired-q KV sharing) -----
// One CTA (128 thr) processes q-tiles qa=pair and qb=31-pair over ONE
// shared KV stream. Half-tile trim: when a subtile's LAST 128-col KV tile
// only has valid columns in its lower half (even qi), compute only 8 of 16
// n-fragments — the skipped columns are exactly the fully-masked ones
// (p = ex2(-huge) = 0), so results are bit-identical.
#define FPITCH 72                          // halves
#define FROWB  144
#define QBUF   (64 * FROWB)                // 9216 B
#define KVBUF  (128 * FROWB)               // 18432 B
#define OFF_QA 0
#define OFF_QB QBUF
#define OFF_KV (2 * QBUF)                  // 18432
#define KVSTG  (2 * KVBUF)                 // 36864 (K + V)
#define SMEM_FLASH (OFF_KV + 2 * KVSTG)    // 92160

__global__ __launch_bounds__(128, 2) void flash_mma(
    const __half* __restrict__ Qh,
    const __half* __restrict__ Kh, const __half* __restrict__ Vh,
    __half* __restrict__ Oh)
{
    extern __shared__ char sm[];
    const uint32_t smb = cvta_smem(sm);
    const int tid = threadIdx.x;
    const int w = tid >> 5, lane = tid & 31;
    const int pair = blockIdx.x;          // 0..15
    const int bh = blockIdx.y;            // 0..63

    const size_t seqbase = (size_t)bh * S_LEN * DK;

    const int qa = pair, qb = 31 - pair;  // qa < qb always
    const int q0a = qa * 64, q0b = qb * 64;
    const int Ta = (qa + 2) >> 1, Tb = (qb + 2) >> 1;
    const bool halfA = (qa & 1) == 0;     // even qi: last tile half-valid
    const bool halfB = (qb & 1) == 0;

    const int laneA = (lane & 15) * FPITCH + ((lane >> 4) & 1) * 8;
    const int laneB = ((lane & 7) + ((lane >> 4) & 1) * 8) * FPITCH + ((lane >> 3) & 1) * 8;
    const int laneV = ((lane & 7) + ((lane >> 3) & 1) * 8) * FPITCH + ((lane >> 4) & 1) * 8;

    const float cs = 0.18033688f;         // (1/8) * log2(e)
    const int b = bh >> 4, h = bh & 15;
    const int cbase = (lane & 3) * 2;

    // load both Q tiles (64 rows each)
#pragma unroll
    for (int i = 0; i < 4; i++) {
        int slot = tid + i * 128;
        int r = slot >> 3, quad = slot & 7;
        uint32_t so = (uint32_t)r * FROWB + (uint32_t)quad * 16u;
        cp16(smb + OFF_QA + so, Qh + seqbase + (size_t)(q0a + r) * DK + quad * 8);
        cp16(smb + OFF_QB + so, Qh + seqbase + (size_t)(q0b + r) * DK + quad * 8);
    }
    auto load_tile = [&](int kt, int stage) {
        const uint32_t sb = smb + OFF_KV + (uint32_t)stage * KVSTG;
#pragma unroll
        for (int i = 0; i < 8; i++) {
            int slot = tid + i * 128;
            int r = slot >> 3, quad = slot & 7;   // r: 0..127
            uint32_t so = (uint32_t)r * FROWB + (uint32_t)quad * 16u;
            size_t g = seqbase + (size_t)(kt * 128 + r) * DK + quad * 8;
            cp16(sb + 0 * KVBUF + so, Kh + g);
            cp16(sb + 1 * KVBUF + so, Vh + g);
        }
    };
    load_tile(0, 0); CP_COMMIT();

    uint32_t qhfA[4][4], qhfB[4][4];
    float oaccA[8][4], oaccB[8][4];
#pragma unroll
    for (int nf = 0; nf < 8; nf++)
#pragma unroll
        for (int j = 0; j < 4; j++) { oaccA[nf][j] = 0.0f; oaccB[nf][j] = 0.0f; }
    float mA0 = -1e30f, mA1 = -1e30f, lA0 = 0.0f, lA1 = 0.0f;
    float mB0 = -1e30f, mB1 = -1e30f, lB0 = 0.0f, lB1 = 0.0f;

    // NFRc: integral constant 8 or 16 = number of n-fragments (cols/8)
    auto process = [&](auto NFRc, const uint32_t (&qhf)[4][4], float (&oacc)[8][4],
                       float& m0r, float& m1r, float& l0r, float& l1r,
                       int q0, bool lastTile, uint32_t kvb, int kt) {
        constexpr int NFR = decltype(NFRc)::value;
        const int rbase = q0 + w * 16 + (lane >> 2);

        // ---- S = Q K^T ----
        float sacc[NFR][4];
#pragma unroll
        for (int nf = 0; nf < NFR; nf++)
#pragma unroll
            for (int j = 0; j < 4; j++) sacc[nf][j] = 0.0f;

#pragma unroll
        for (int ks = 0; ks < 4; ks++) {
            uint32_t kb[2 * NFR];
#pragma unroll
            for (int nb = 0; nb < NFR / 2; nb++) {
                uint32_t a = kvb + (uint32_t)((nb * 16) * FPITCH + ks * 16 + laneB) * 2;
                ldsm4(kb + nb * 4, a);
            }
#pragma unroll
            for (int nf = 0; nf < NFR; nf++) {
                int bi = (nf >> 1) * 4 + (nf & 1) * 2;
                mma16816(sacc[nf], qhf[ks], kb[bi], kb[bi + 1]);
            }
        }

        // ---- scale (+ causal mask on the last tile) ----
        if (lastTile) {
#pragma unroll
            for (int nf = 0; nf < NFR; nf++) {
#pragma unroll
                for (int j = 0; j < 4; j++) {
                    int col = kt * 128 + nf * 8 + cbase + (j & 1);
                    int row = rbase + ((j >> 1) << 3);
                    sacc[nf][j] = (col <= row) ? sacc[nf][j] * cs : -1e30f;
                }
            }
        } else {
#pragma unroll
            for (int nf = 0; nf < NFR; nf++)
#pragma unroll
                for (int j = 0; j < 4; j++) sacc[nf][j] *= cs;
        }

        // ---- online softmax (base-2) ----
        float mx0 = -1e30f, mx1 = -1e30f;
#pragma unroll
        for (int nf = 0; nf < NFR; nf++) {
            mx0 = fmaxf(mx0, fmaxf(sacc[nf][0], sacc[nf][1]));
            mx1 = fmaxf(mx1, fmaxf(sacc[nf][2], sacc[nf][3]));
        }
        mx0 = fmaxf(mx0, __shfl_xor_sync(0xffffffffu, mx0, 1));
        mx0 = fmaxf(mx0, __shfl_xor_sync(0xffffffffu, mx0, 2));
        mx1 = fmaxf(mx1, __shfl_xor_sync(0xffffffffu, mx1, 1));
        mx1 = fmaxf(mx1, __shfl_xor_sync(0xffffffffu, mx1, 2));

        float mn0 = fmaxf(m0r, mx0), mn1 = fmaxf(m1r, mx1);
        float c0 = ex2(m0r - mn0), c1 = ex2(m1r - mn1);
        m0r = mn0; m1r = mn1;

        uint32_t pHa[NFR], pHb[NFR];
        float ls0 = 0.0f, ls1 = 0.0f;
#pragma unroll
        for (int nf = 0; nf < NFR; nf++) {
            float p0 = ex2(sacc[nf][0] - mn0);
            float p1 = ex2(sacc[nf][1] - mn0);
            float p2 = ex2(sacc[nf][2] - mn1);
            float p3 = ex2(sacc[nf][3] - mn1);
            ls0 += p0 + p1;
            ls1 += p2 + p3;
            __half2 h01 = __floats2half2_rn(p0, p1);
            __half2 h23 = __floats2half2_rn(p2, p3);
            pHa[nf] = *(uint32_t*)&h01;
            pHb[nf] = *(uint32_t*)&h23;
        }
        ls0 += __shfl_xor_sync(0xffffffffu, ls0, 1);
        ls0 += __shfl_xor_sync(0xffffffffu, ls0, 2);
        ls1 += __shfl_xor_sync(0xffffffffu, ls1, 1);
        ls1 += __shfl_xor_sync(0xffffffffu, ls1, 2);
        l0r = l0r * c0 + ls0;
        l1r = l1r * c1 + ls1;
#pragma unroll
        for (int nf = 0; nf < 8; nf++) {
            oacc[nf][0] *= c0; oacc[nf][1] *= c0;
            oacc[nf][2] *= c1; oacc[nf][3] *= c1;
        }

        // ---- O += P V  (skip ks >= NFR/2: those P cols are exactly 0) ----
        const uint32_t vbb = kvb + KVBUF;
#pragma unroll
        for (int ks = 0; ks < NFR / 2; ks++) {
            uint32_t vb[16];
#pragma unroll
            for (int nb = 0; nb < 4; nb++) {
                uint32_t a = vbb + (uint32_t)((ks * 16) * FPITCH + nb * 16 + laneV) * 2;
                ldsm4t(vb + nb * 4, a);
            }
            uint32_t pa[4] = { pHa[2 * ks], pHb[2 * ks],
                               pHa[2 * ks + 1], pHb[2 * ks + 1] };
#pragma unroll
            for (int nf = 0; nf < 8; nf++) {
                int bi = (nf >> 1) * 4 + (nf & 1) * 2;
                mma16816(oacc[nf], pa, vb[bi], vb[bi + 1]);
            }
        }
    };

    for (int kt = 0; kt < Tb; kt++) {
        CP_WAIT(0);
        __syncthreads();

        if (kt == 0) {
#pragma unroll
            for (int ks = 0; ks < 4; ks++) {
                uint32_t off = (uint32_t)((w * 16) * FPITCH + ks * 16 + laneA) * 2;
                ldsm4(qhfA[ks], smb + OFF_QA + off);
                ldsm4(qhfB[ks], smb + OFF_QB + off);
            }
        }
        if (kt + 1 < Tb) {
            load_tile(kt + 1, (kt + 1) & 1);
            CP_COMMIT();
        }

        const uint32_t kvb = smb + OFF_KV + (uint32_t)(kt & 1) * KVSTG;

        const bool lastB = (kt == Tb - 1);
        if (lastB && halfB)
            process(IC<8>{}, qhfB, oaccB, mB0, mB1, lB0, lB1, q0b, true, kvb, kt);
        else
            process(IC<16>{}, qhfB, oaccB, mB0, mB1, lB0, lB1, q0b, lastB, kvb, kt);

        if (kt < Ta) {
            const bool lastA = (kt == Ta - 1);
            if (lastA && halfA)
                process(IC<8>{}, qhfA, oaccA, mA0, mA1, lA0, lA1, q0a, true, kvb, kt);
            else
                process(IC<16>{}, qhfA, oaccA, mA0, mA1, lA0, lA1, q0a, lastA, kvb, kt);
        }
    }

    // ---- epilogue: write fp16 context [B,S,1024] for both q-tiles ----
#pragma unroll
    for (int which = 0; which < 2; which++) {
        float (*oacc)[4] = which ? oaccB : oaccA;
        const float inv0 = 1.0f / (which ? lB0 : lA0);
        const float inv1 = 1.0f / (which ? lB1 : lA1);
        const int q0 = which ? q0b : q0a;
        const int s0 = q0 + w * 16 + (lane >> 2);
#pragma unroll
        for (int nf = 0; nf < 8; nf++) {
            int col = h * DK + nf * 8 + cbase;
#pragma unroll
            for (int hh = 0; hh < 2; hh++) {
                int s = s0 + hh * 8;
                float vx = oacc[nf][hh * 2 + 0] * (hh ? inv1 : inv0);
                float vy = oacc[nf][hh * 2 + 1] * (hh ? inv1 : inv0);
                size_t idx = ((size_t)(b * S_LEN + s)) * DMODEL + col;
                *(__half2*)(Oh + idx) = __floats2half2_rn(vx, vy);
            }
        }
    }
}

// ===========================================================================
extern "C" void kernel_launch(void* const* d_in, const int* in_sizes, int n_in,
                              void* d_out, int out_size)
{
    const float* query = (const float*)d_in[0];
    const float* key   = (const float*)d_in[1];
    const float* value = (const float*)d_in[2];
    // d_in[3] = causal mask — handled analytically.
    const float* Wq = (const float*)d_in[4];
    const float* bq = (const float*)d_in[5];
    const float* Wk = (const float*)d_in[6];
    const float* bk = (const float*)d_in[7];
    const float* Wv = (const float*)d_in[8];
    const float* bv = (const float*)d_in[9];
    const float* Wo = (const float*)d_in[10];
    const float* bo = (const float*)d_in[11];
    float* out = (float*)d_out;

    __half *Aq, *Ak, *Av, *Qh, *Kh, *Vh, *Wqh, *Wkh, *Wvh, *Woh;
    cudaGetSymbolAddress((void**)&Aq, g_Aq);
    cudaGetSymbolAddress((void**)&Ak, g_Ak);
    cudaGetSymbolAddress((void**)&Av, g_Av);
    cudaGetSymbolAddress((void**)&Qh, g_Qh);
    cudaGetSymbolAddress((void**)&Kh, g_Kh);
    cudaGetSymbolAddress((void**)&Vh, g_Vh);
    cudaGetSymbolAddress((void**)&Wqh, g_Wqh);
    cudaGetSymbolAddress((void**)&Wkh, g_Wkh);
    cudaGetSymbolAddress((void**)&Wvh, g_Wvh);
    cudaGetSymbolAddress((void**)&Woh, g_Woh);

    cudaFuncSetAttribute(proj_gemm_mma<1>,
                         cudaFuncAttributeMaxDynamicSharedMemorySize, SMEM_GEMM);
    cudaFuncSetAttribute(proj_gemm_mma<0>,
                         cudaFuncAttributeMaxDynamicSharedMemorySize, SMEM_GEMM);
    cudaFuncSetAttribute(flash_mma,
                         cudaFuncAttributeMaxDynamicSharedMemorySize, SMEM_FLASH);

    // one consolidated conversion pass
    split_all<<<SPLIT_GRID, 256>>>(
        (const float4*)query, (const float4*)key, (const float4*)value,
        (const float4*)Wq, (const float4*)Wk, (const float4*)Wv, (const float4*)Wo,
        (uint2*)Aq, (uint2*)Ak, (uint2*)Av,
        (uint2*)Wqh, (uint2*)Wkh, (uint2*)Wvh, (uint2*)Woh);

    // Q, K, V projections batched in one launch
    dim3 gq(DMODEL / TILE_N, MTOT / TILE_M, 3);   // (16, 64, 3)
    proj_gemm_mma<1><<<gq, 128, SMEM_GEMM>>>(
        Aq, Ak, Av, Wqh, Wkh, Wvh, bq, bk, bv, Qh, Kh, Vh, nullptr);

    // attention: paired q-tiles, writes fp16 context into Aq
    flash_mma<<<dim3(16, BATCH * NHEAD), 128, SMEM_FLASH>>>(Qh, Kh, Vh, Aq);

    // out = Ctx @ Wo^T + bo (fp32 out)
    dim3 go(DMODEL / TILE_N, MTOT / TILE_M, 1);   // (16, 64)
    proj_gemm_mma<0><<<go, 128, SMEM_GEMM>>>(
        Aq, nullptr, nullptr, Woh, nullptr, nullptr,
        bo, nullptr, nullptr, nullptr, nullptr, nullptr, out);
}

// round 16
// speedup vs baseline: 1.0210x; 1.0144x over previous
#include <cuda_runtime.h>
#include <cuda_fp16.h>
#include <cstdint>

#define S_LEN  2048
#define DMODEL 1024
#define NHEAD  16
#define DK     64
#define BATCH  4
#define MTOT   (BATCH * S_LEN)     // 8192

// ---------------- scratch (module-scope device memory) ----------------
__device__ __half g_Aq[MTOT * DMODEL];   // query f16 (later: ctx f16)
__device__ __half g_Ak[MTOT * DMODEL];   // key f16
__device__ __half g_Av[MTOT * DMODEL];   // value f16
__device__ __half g_Qh[BATCH * NHEAD * S_LEN * DK];
__device__ __half g_Kh[BATCH * NHEAD * S_LEN * DK];
__device__ __half g_Vh[BATCH * NHEAD * S_LEN * DK];
__device__ __half g_Wqh[DMODEL * DMODEL];
__device__ __half g_Wkh[DMODEL * DMODEL];
__device__ __half g_Wvh[DMODEL * DMODEL];
__device__ __half g_Woh[DMODEL * DMODEL];

// ---------------- PTX helpers (baseline PTX only) ----------------------
__device__ __forceinline__ uint32_t cvta_smem(const void* p) {
    uint32_t a;
    asm("{ .reg .u64 t; cvta.to.shared.u64 t, %1; cvt.u32.u64 %0, t; }"
        : "=r"(a) : "l"(p));
    return a;
}
__device__ __forceinline__ void cp16(uint32_t dst, const void* src) {
    asm volatile("cp.async.cg.shared.global [%0], [%1], 16;"
                 :: "r"(dst), "l"(src));
}
#define CP_COMMIT() asm volatile("cp.async.commit_group;" ::: "memory")
#define CP_WAIT(n)  asm volatile("cp.async.wait_group %0;" :: "n"(n) : "memory")

__device__ __forceinline__ void ldsm4(uint32_t* r, uint32_t addr) {
    asm volatile("ldmatrix.sync.aligned.m8n8.x4.shared.b16 {%0,%1,%2,%3}, [%4];"
                 : "=r"(r[0]), "=r"(r[1]), "=r"(r[2]), "=r"(r[3]) : "r"(addr));
}
__device__ __forceinline__ void ldsm4t(uint32_t* r, uint32_t addr) {
    asm volatile("ldmatrix.sync.aligned.m8n8.x4.trans.shared.b16 {%0,%1,%2,%3}, [%4];"
                 : "=r"(r[0]), "=r"(r[1]), "=r"(r[2]), "=r"(r[3]) : "r"(addr));
}
__device__ __forceinline__ void mma16816(float* d, const uint32_t* a,
                                         uint32_t b0, uint32_t b1) {
    asm volatile(
        "mma.sync.aligned.m16n8k16.row.col.f32.f16.f16.f32 "
        "{%0,%1,%2,%3}, {%4,%5,%6,%7}, {%8,%9}, {%0,%1,%2,%3};"
        : "+f"(d[0]), "+f"(d[1]), "+f"(d[2]), "+f"(d[3])
        : "r"(a[0]), "r"(a[1]), "r"(a[2]), "r"(a[3]), "r"(b0), "r"(b1));
}
__device__ __forceinline__ float ex2(float x) {
    float y;
    asm("ex2.approx.f32 %0, %1;" : "=f"(y) : "f"(x));
    return y;
}

__device__ __forceinline__ uint2 pack_hi(float4 v) {
    __half h0 = __float2half_rn(v.x), h1 = __float2half_rn(v.y);
    __half h2 = __float2half_rn(v.z), h3 = __float2half_rn(v.w);
    uint2 H;
    H.x = (uint32_t)__half_as_ushort(h0) | ((uint32_t)__half_as_ushort(h1) << 16);
    H.y = (uint32_t)__half_as_ushort(h2) | ((uint32_t)__half_as_ushort(h3) << 16);
    return H;
}

// ---------------- single consolidated split kernel (MLP=4) --------------
#define ACT_BLKS  2048        // (MTOT*DMODEL/4)/256/4
#define W_BLKS    256         // (DMODEL*DMODEL/4)/256/4
#define SPLIT_GRID (3 * ACT_BLKS + 4 * W_BLKS)

__global__ __launch_bounds__(256) void split_all(
    const float4* __restrict__ q, const float4* __restrict__ k,
    const float4* __restrict__ v,
    const float4* __restrict__ wq, const float4* __restrict__ wk,
    const float4* __restrict__ wv, const float4* __restrict__ wo,
    uint2* __restrict__ aq, uint2* __restrict__ ak, uint2* __restrict__ av,
    uint2* __restrict__ wqh, uint2* __restrict__ wkh,
    uint2* __restrict__ wvh, uint2* __restrict__ woh)
{
    const int b = blockIdx.x, t = threadIdx.x;
    const float4* src;
    uint2* dst;
    int base;
    if (b < 3 * ACT_BLKS) {
        const int which = b / ACT_BLKS;
        base = (b % ACT_BLKS) * 1024 + t;
        src = which == 0 ? q : (which == 1 ? k : v);
        dst = which == 0 ? aq : (which == 1 ? ak : av);
    } else {
        const int wb = b - 3 * ACT_BLKS;
        const int which = wb / W_BLKS;
        base = (wb % W_BLKS) * 1024 + t;
        src = which == 0 ? wq : (which == 1 ? wk : (which == 2 ? wv : wo));
        dst = which == 0 ? wqh : (which == 1 ? wkh : (which == 2 ? wvh : woh));
    }
    float4 v0 = src[base];
    float4 v1 = src[base + 256];
    float4 v2 = src[base + 512];
    float4 v3 = src[base + 768];
    dst[base]       = pack_hi(v0);
    dst[base + 256] = pack_hi(v1);
    dst[base + 512] = pack_hi(v2);
    dst[base + 768] = pack_hi(v3);
}

// ---------------- HMMA projection GEMM (128x64 tile, 3 CTAs/SM) ---------
// Single __syncthreads per K-chunk (R15-measured best: 57.2us).
#define TILE_M 128
#define TILE_N 64
#define KCH    64
#define NC     (DMODEL / KCH)  // 16
#define PITCH  72              // halves per smem row (144B)
#define ROWB   144
#define A_OFF  0
#define B_OFF  (128 * ROWB)              // 18432
#define STG_B  (B_OFF + 64 * ROWB)       // 27648
#define SMEM_GEMM (2 * STG_B)            // 55296

template <int QKV>
__global__ __launch_bounds__(128, 3) void proj_gemm_mma(
    const __half* __restrict__ A0, const __half* __restrict__ A1,
    const __half* __restrict__ A2,
    const __half* __restrict__ W0, const __half* __restrict__ W1,
    const __half* __restrict__ W2,
    const float* __restrict__ b0, const float* __restrict__ b1,
    const float* __restrict__ b2,
    __half* __restrict__ C0, __half* __restrict__ C1,
    __half* __restrict__ C2, float* __restrict__ Cf)
{
    extern __shared__ char sm[];
    const uint32_t smb = cvta_smem(sm);
    const int tid = threadIdx.x;
    const int wid = tid >> 5, lane = tid & 31;
    const int wm = wid & 1;
    const int wn = wid >> 1;
    const int m0 = blockIdx.y * TILE_M;
    const int n0 = blockIdx.x * TILE_N;

    const __half* Ahg; const __half* Whg; const float* bias; __half* Ch;
    if (QKV) {
        const int z = blockIdx.z;
        Ahg  = z == 0 ? A0 : (z == 1 ? A1 : A2);
        Whg  = z == 0 ? W0 : (z == 1 ? W1 : W2);
        bias = z == 0 ? b0 : (z == 1 ? b1 : b2);
        Ch   = z == 0 ? C0 : (z == 1 ? C1 : C2);
    } else {
        Ahg = A0; Whg = W0; bias = b0; Ch = nullptr;
    }

    const int laneA = (lane & 15) * PITCH + ((lane >> 4) & 1) * 8;
    const int laneB = ((lane & 7) + ((lane >> 4) & 1) * 8) * PITCH + ((lane >> 3) & 1) * 8;

    auto load_chunk = [&](int c, int stage) {
        const uint32_t sbase = smb + (uint32_t)stage * STG_B;
#pragma unroll
        for (int i = 0; i < 8; i++) {
            int slot = tid + i * 128;
            int row = slot >> 3, quad = slot & 7;
            uint32_t soff = (uint32_t)row * ROWB + (uint32_t)quad * 16u;
            size_t goff = (size_t)(m0 + row) * DMODEL + c * KCH + quad * 8;
            cp16(sbase + A_OFF + soff, Ahg + goff);
        }
#pragma unroll
        for (int i = 0; i < 4; i++) {
            int slot = tid + i * 128;
            int row = slot >> 3, quad = slot & 7;
            uint32_t soff = (uint32_t)row * ROWB + (uint32_t)quad * 16u;
            size_t goff = (size_t)(n0 + row) * DMODEL + c * KCH + quad * 8;
            cp16(sbase + B_OFF + soff, Whg + goff);
        }
    };

    float acc[4][4][4];
#pragma unroll
    for (int mf = 0; mf < 4; mf++)
#pragma unroll
        for (int nf = 0; nf < 4; nf++)
#pragma unroll
            for (int j = 0; j < 4; j++) acc[mf][nf][j] = 0.0f;

    load_chunk(0, 0); CP_COMMIT();

    for (int c = 0; c < NC; c++) {
        CP_WAIT(0);
        __syncthreads();          // also orders compute(c-1) before load(c+1)
        if (c + 1 < NC) {
            load_chunk(c + 1, (c + 1) & 1);
            CP_COMMIT();
        }

        const uint32_t sbase = smb + (uint32_t)(c & 1) * STG_B;

#pragma unroll
        for (int ks = 0; ks < 4; ks++) {
            const int kk = ks * 16;
            uint32_t ah[4][4], bh[8];
#pragma unroll
            for (int mf = 0; mf < 4; mf++) {
                uint32_t idx = (uint32_t)((wm * 64 + mf * 16) * PITCH + kk + laneA) * 2;
                ldsm4(ah[mf], sbase + A_OFF + idx);
            }
#pragma unroll
            for (int nf2 = 0; nf2 < 2; nf2++) {
                uint32_t idx = (uint32_t)((wn * 32 + nf2 * 16) * PITCH + kk + laneB) * 2;
                ldsm4(bh + nf2 * 4, sbase + B_OFF + idx);
            }
#pragma unroll
            for (int mf = 0; mf < 4; mf++)
#pragma unroll
                for (int nf = 0; nf < 4; nf++) {
                    int bi = (nf >> 1) * 4 + (nf & 1) * 2;
                    mma16816(acc[mf][nf], ah[mf], bh[bi], bh[bi + 1]);
                }
        }
    }

    // epilogue
#pragma unroll
    for (int mf = 0; mf < 4; mf++) {
#pragma unroll
        for (int nf = 0; nf < 4; nf++) {
            int m = m0 + wm * 64 + mf * 16 + (lane >> 2);
            int n = n0 + wn * 32 + nf * 8 + (lane & 3) * 2;
            float bx = bias[n], by = bias[n + 1];
#pragma unroll
            for (int hh = 0; hh < 2; hh++) {
                int mm = m + hh * 8;
                float vx = acc[mf][nf][hh * 2 + 0] + bx;
                float vy = acc[mf][nf][hh * 2 + 1] + by;
                if (QKV) {
                    int b = mm >> 11, s = mm & (S_LEN - 1);
                    int h = n >> 6, d = n & (DK - 1);
                    size_t idx = ((size_t)((b << 4) + h) * S_LEN + s) * DK + d;
                    *(__half2*)(Ch + idx) = __floats2half2_rn(vx, vy);
                } else {
                    float2 v; v.x = vx; v.y = vy;
                    *(float2*)(Cf + (size_t)mm * DMODEL + n) = v;
                }
            }
        }
    }
}

// ---------------- HMMA causal flash attention (paired-q KV sharing) -----
// Exact R13-measured body: one 16-fragment process path, Q-ldsm before
// prefetch at kt==0. One CTA (128 thr) handles q-tiles qa=pair, qb=31-pair
// over one shared KV stream (qa's tiles are a prefix of qb's).
#define FPITCH 72                          // halves
#define FROWB  144
#define QBUF   (64 * FROWB)                // 9216 B
#define KVBUF  (128 * FROWB)               // 18432 B
#define OFF_QA 0
#define OFF_QB QBUF
#define OFF_KV (2 * QBUF)                  // 18432
#define KVSTG  (2 * KVBUF)                 // 36864 (K + V)
#define SMEM_FLASH (OFF_KV + 2 * KVSTG)    // 92160

__global__ __launch_bounds__(128, 2) void flash_mma(
    const __half* __restrict__ Qh,
    const __half* __restrict__ Kh, const __half* __restrict__ Vh,
    __half* __restrict__ Oh)
{
    extern __shared__ char sm[];
    const uint32_t smb = cvta_smem(sm);
    const int tid = threadIdx.x;
    const int w = tid >> 5, lane = tid & 31;
    const int pair = blockIdx.x;          // 0..15
    const int bh = blockIdx.y;            // 0..63

    const size_t seqbase = (size_t)bh * S_LEN * DK;

    const int qa = pair, qb = 31 - pair;  // qa < qb always
    const int q0a = qa * 64, q0b = qb * 64;
    const int Ta = (qa + 2) >> 1, Tb = (qb + 2) >> 1;

    const int laneA = (lane & 15) * FPITCH + ((lane >> 4) & 1) * 8;
    const int laneB = ((lane & 7) + ((lane >> 4) & 1) * 8) * FPITCH + ((lane >> 3) & 1) * 8;
    const int laneV = ((lane & 7) + ((lane >> 3) & 1) * 8) * FPITCH + ((lane >> 4) & 1) * 8;

    const float cs = 0.18033688f;         // (1/8) * log2(e)
    const int b = bh >> 4, h = bh & 15;
    const int cbase = (lane & 3) * 2;

    // load both Q tiles (64 rows each)
#pragma unroll
    for (int i = 0; i < 4; i++) {
        int slot = tid + i * 128;
        int r = slot >> 3, quad = slot & 7;
        uint32_t so = (uint32_t)r * FROWB + (uint32_t)quad * 16u;
        cp16(smb + OFF_QA + so, Qh + seqbase + (size_t)(q0a + r) * DK + quad * 8);
        cp16(smb + OFF_QB + so, Qh + seqbase + (size_t)(q0b + r) * DK + quad * 8);
    }
    auto load_tile = [&](int kt, int stage) {
        const uint32_t sb = smb + OFF_KV + (uint32_t)stage * KVSTG;
#pragma unroll
        for (int i = 0; i < 8; i++) {
            int slot = tid + i * 128;
            int r = slot >> 3, quad = slot & 7;   // r: 0..127
            uint32_t so = (uint32_t)r * FROWB + (uint32_t)quad * 16u;
            size_t g = seqbase + (size_t)(kt * 128 + r) * DK + quad * 8;
            cp16(sb + 0 * KVBUF + so, Kh + g);
            cp16(sb + 1 * KVBUF + so, Vh + g);
        }
    };
    load_tile(0, 0); CP_COMMIT();

    uint32_t qhfA[4][4], qhfB[4][4];
    float oaccA[8][4], oaccB[8][4];
#pragma unroll
    for (int nf = 0; nf < 8; nf++)
#pragma unroll
        for (int j = 0; j < 4; j++) { oaccA[nf][j] = 0.0f; oaccB[nf][j] = 0.0f; }
    float mA0 = -1e30f, mA1 = -1e30f, lA0 = 0.0f, lA1 = 0.0f;
    float mB0 = -1e30f, mB1 = -1e30f, lB0 = 0.0f, lB1 = 0.0f;

    auto process = [&](const uint32_t (&qhf)[4][4], float (&oacc)[8][4],
                       float& m0r, float& m1r, float& l0r, float& l1r,
                       int q0, bool lastTile, uint32_t kvb, int kt) {
        const int rbase = q0 + w * 16 + (lane >> 2);

        // ---- S = Q K^T ----
        float sacc[16][4];
#pragma unroll
        for (int nf = 0; nf < 16; nf++)
#pragma unroll
            for (int j = 0; j < 4; j++) sacc[nf][j] = 0.0f;

#pragma unroll
        for (int ks = 0; ks < 4; ks++) {
            uint32_t kb[32];
#pragma unroll
            for (int nb = 0; nb < 8; nb++) {
                uint32_t a = kvb + (uint32_t)((nb * 16) * FPITCH + ks * 16 + laneB) * 2;
                ldsm4(kb + nb * 4, a);
            }
#pragma unroll
            for (int nf = 0; nf < 16; nf++) {
                int bi = (nf >> 1) * 4 + (nf & 1) * 2;
                mma16816(sacc[nf], qhf[ks], kb[bi], kb[bi + 1]);
            }
        }

        // ---- scale (+ causal mask on the last tile) ----
        if (lastTile) {
#pragma unroll
            for (int nf = 0; nf < 16; nf++) {
#pragma unroll
                for (int j = 0; j < 4; j++) {
                    int col = kt * 128 + nf * 8 + cbase + (j & 1);
                    int row = rbase + ((j >> 1) << 3);
                    sacc[nf][j] = (col <= row) ? sacc[nf][j] * cs : -1e30f;
                }
            }
        } else {
#pragma unroll
            for (int nf = 0; nf < 16; nf++)
#pragma unroll
                for (int j = 0; j < 4; j++) sacc[nf][j] *= cs;
        }

        // ---- online softmax (base-2) ----
        float mx0 = -1e30f, mx1 = -1e30f;
#pragma unroll
        for (int nf = 0; nf < 16; nf++) {
            mx0 = fmaxf(mx0, fmaxf(sacc[nf][0], sacc[nf][1]));
            mx1 = fmaxf(mx1, fmaxf(sacc[nf][2], sacc[nf][3]));
        }
        mx0 = fmaxf(mx0, __shfl_xor_sync(0xffffffffu, mx0, 1));
        mx0 = fmaxf(mx0, __shfl_xor_sync(0xffffffffu, mx0, 2));
        mx1 = fmaxf(mx1, __shfl_xor_sync(0xffffffffu, mx1, 1));
        mx1 = fmaxf(mx1, __shfl_xor_sync(0xffffffffu, mx1, 2));

        float mn0 = fmaxf(m0r, mx0), mn1 = fmaxf(m1r, mx1);
        float c0 = ex2(m0r - mn0), c1 = ex2(m1r - mn1);
        m0r = mn0; m1r = mn1;

        uint32_t pHa[16], pHb[16];
        float ls0 = 0.0f, ls1 = 0.0f;
#pragma unroll
        for (int nf = 0; nf < 16; nf++) {
            float p0 = ex2(sacc[nf][0] - mn0);
            float p1 = ex2(sacc[nf][1] - mn0);
            float p2 = ex2(sacc[nf][2] - mn1);
            float p3 = ex2(sacc[nf][3] - mn1);
            ls0 += p0 + p1;
            ls1 += p2 + p3;
            __half2 h01 = __floats2half2_rn(p0, p1);
            __half2 h23 = __floats2half2_rn(p2, p3);
            pHa[nf] = *(uint32_t*)&h01;
            pHb[nf] = *(uint32_t*)&h23;
        }
        ls0 += __shfl_xor_sync(0xffffffffu, ls0, 1);
        ls0 += __shfl_xor_sync(0xffffffffu, ls0, 2);
        ls1 += __shfl_xor_sync(0xffffffffu, ls1, 1);
        ls1 += __shfl_xor_sync(0xffffffffu, ls1, 2);
        l0r = l0r * c0 + ls0;
        l1r = l1r * c1 + ls1;
#pragma unroll
        for (int nf = 0; nf < 8; nf++) {
            oacc[nf][0] *= c0; oacc[nf][1] *= c0;
            oacc[nf][2] *= c1; oacc[nf][3] *= c1;
        }

        // ---- O += P V ----
        const uint32_t vbb = kvb + KVBUF;
#pragma unroll
        for (int ks = 0; ks < 8; ks++) {
            uint32_t vb[16];
#pragma unroll
            for (int nb = 0; nb < 4; nb++) {
                uint32_t a = vbb + (uint32_t)((ks * 16) * FPITCH + nb * 16 + laneV) * 2;
                ldsm4t(vb + nb * 4, a);
            }
            uint32_t pa[4] = { pHa[2 * ks], pHb[2 * ks],
                               pHa[2 * ks + 1], pHb[2 * ks + 1] };
#pragma unroll
            for (int nf = 0; nf < 8; nf++) {
                int bi = (nf >> 1) * 4 + (nf & 1) * 2;
                mma16816(oacc[nf], pa, vb[bi], vb[bi + 1]);
            }
        }
    };

    for (int kt = 0; kt < Tb; kt++) {
        CP_WAIT(0);
        __syncthreads();

        if (kt == 0) {
#pragma unroll
            for (int ks = 0; ks < 4; ks++) {
                uint32_t off = (uint32_t)((w * 16) * FPITCH + ks * 16 + laneA) * 2;
                ldsm4(qhfA[ks], smb + OFF_QA + off);
                ldsm4(qhfB[ks], smb + OFF_QB + off);
            }
        }
        if (kt + 1 < Tb) {
            load_tile(kt + 1, (kt + 1) & 1);
            CP_COMMIT();
        }

        const uint32_t kvb = smb + OFF_KV + (uint32_t)(kt & 1) * KVSTG;

        process(qhfB, oaccB, mB0, mB1, lB0, lB1, q0b, kt == Tb - 1, kvb, kt);
        if (kt < Ta)
            process(qhfA, oaccA, mA0, mA1, lA0, lA1, q0a, kt == Ta - 1, kvb, kt);
    }

    // ---- epilogue: write fp16 context [B,S,1024] for both q-tiles ----
#pragma unroll
    for (int which = 0; which < 2; which++) {
        float (*oacc)[4] = which ? oaccB : oaccA;
        const float inv0 = 1.0f / (which ? lB0 : lA0);
        const float inv1 = 1.0f / (which ? lB1 : lA1);
        const int q0 = which ? q0b : q0a;
        const int s0 = q0 + w * 16 + (lane >> 2);
#pragma unroll
        for (int nf = 0; nf < 8; nf++) {
            int col = h * DK + nf * 8 + cbase;
#pragma unroll
            for (int hh = 0; hh < 2; hh++) {
                int s = s0 + hh * 8;
                float vx = oacc[nf][hh * 2 + 0] * (hh ? inv1 : inv0);
                float vy = oacc[nf][hh * 2 + 1] * (hh ? inv1 : inv0);
                size_t idx = ((size_t)(b * S_LEN + s)) * DMODEL + col;
                *(__half2*)(Oh + idx) = __floats2half2_rn(vx, vy);
            }
        }
    }
}

// ===========================================================================
extern "C" void kernel_launch(void* const* d_in, const int* in_sizes, int n_in,
                              void* d_out, int out_size)
{
    const float* query = (const float*)d_in[0];
    const float* key   = (const float*)d_in[1];
    const float* value = (const float*)d_in[2];
    // d_in[3] = causal mask — handled analytically.
    const float* Wq = (const float*)d_in[4];
    const float* bq = (const float*)d_in[5];
    const float* Wk = (const float*)d_in[6];
    const float* bk = (const float*)d_in[7];
    const float* Wv = (const float*)d_in[8];
    const float* bv = (const float*)d_in[9];
    const float* Wo = (const float*)d_in[10];
    const float* bo = (const float*)d_in[11];
    float* out = (float*)d_out;

    __half *Aq, *Ak, *Av, *Qh, *Kh, *Vh, *Wqh, *Wkh, *Wvh, *Woh;
    cudaGetSymbolAddress((void**)&Aq, g_Aq);
    cudaGetSymbolAddress((void**)&Ak, g_Ak);
    cudaGetSymbolAddress((void**)&Av, g_Av);
    cudaGetSymbolAddress((void**)&Qh, g_Qh);
    cudaGetSymbolAddress((void**)&Kh, g_Kh);
    cudaGetSymbolAddress((void**)&Vh, g_Vh);
    cudaGetSymbolAddress((void**)&Wqh, g_Wqh);
    cudaGetSymbolAddress((void**)&Wkh, g_Wkh);
    cudaGetSymbolAddress((void**)&Wvh, g_Wvh);
    cudaGetSymbolAddress((void**)&Woh, g_Woh);

    cudaFuncSetAttribute(proj_gemm_mma<1>,
                         cudaFuncAttributeMaxDynamicSharedMemorySize, SMEM_GEMM);
    cudaFuncSetAttribute(proj_gemm_mma<0>,
                         cudaFuncAttributeMaxDynamicSharedMemorySize, SMEM_GEMM);
    cudaFuncSetAttribute(flash_mma,
                         cudaFuncAttributeMaxDynamicSharedMemorySize, SMEM_FLASH);

    // one consolidated conversion pass
    split_all<<<SPLIT_GRID, 256>>>(
        (const float4*)query, (const float4*)key, (const float4*)value,
        (const float4*)Wq, (const float4*)Wk, (const float4*)Wv, (const float4*)Wo,
        (uint2*)Aq, (uint2*)Ak, (uint2*)Av,
        (uint2*)Wqh, (uint2*)Wkh, (uint2*)Wvh, (uint2*)Woh);

    // Q, K, V projections batched in one launch
    dim3 gq(DMODEL / TILE_N, MTOT / TILE_M, 3);   // (16, 64, 3)
    proj_gemm_mma<1><<<gq, 128, SMEM_GEMM>>>(
        Aq, Ak, Av, Wqh, Wkh, Wvh, bq, bk, bv, Qh, Kh, Vh, nullptr);

    // attention: paired q-tiles, writes fp16 context into Aq
    flash_mma<<<dim3(16, BATCH * NHEAD), 128, SMEM_FLASH>>>(Qh, Kh, Vh, Aq);

    // out = Ctx @ Wo^T + bo (fp32 out)
    dim3 go(DMODEL / TILE_N, MTOT / TILE_M, 1);   // (16, 64)
    proj_gemm_mma<0><<<go, 128, SMEM_GEMM>>>(
        Aq, nullptr, nullptr, Woh, nullptr, nullptr,
        bo, nullptr, nullptr, nullptr, nullptr, nullptr, out);
}